// round 11
// baseline (speedup 1.0000x reference)
#include <cuda_runtime.h>
#include <cstdint>
#include <cub/block/block_scan.cuh>

// Problem constants (fixed shapes from reference)
#define B_BATCH 4
#define C_CLS   19
#define HW      (512 * 512)            // 262144
#define P_PIX   (B_BATCH * HW)         // 1048576

// 16-bit quantization of err in [0,1]: fp32 bits[29:14] (7 exp + 9 mantissa),
// extracted sign-safely as (bits<<2)>>16. Measured loss error 6.3e-8.
#define QBITS 16
#define NB_PER_CLASS (1 << QBITS)          // 65536
#define QMASK (NB_PER_CLASS - 1)
#define NB (C_CLS * NB_PER_CLASS)          // 1,245,184

#define CHUNK 4096
#define CHUNKS_PER_CLASS 16
#define NCHUNK (NB / CHUNK)                // 304 (16 per class)

// Histogram: u32 per bucket, packed cnt | gt<<16. Bucket ids stored
// BIT-REVERSED (self-inverse): the 8 buckets per 32B L2 sector are qd values
// 8192 apart -> concurrent REDs never serialize on a sector (R8/R9-proven).
__device__ __align__(16) uint32_t g_hist[NB];
__device__ unsigned long long g_chunkSum[NCHUNK];
// Sync block: zeroed by one 16B memset each replay.
__device__ __align__(16) struct { unsigned int done; unsigned int done2;
                                  double loss; } g_sync;

// ---------------------------------------------------------------------------
// f32x2 packed-math helpers (FFMA2: 2 fp32 FMAs per issue slot)
// ---------------------------------------------------------------------------
__device__ __forceinline__ unsigned long long pk2(float lo, float hi) {
    unsigned long long r;
    asm("mov.b64 %0, {%1, %2};" : "=l"(r) : "f"(lo), "f"(hi));
    return r;
}
__device__ __forceinline__ unsigned long long ffma2(unsigned long long a,
                                                    unsigned long long b,
                                                    unsigned long long c) {
    unsigned long long d;
    asm("fma.rn.f32x2 %0, %1, %2, %3;" : "=l"(d) : "l"(a), "l"(b), "l"(c));
    return d;
}
__device__ __forceinline__ unsigned long long fadd2(unsigned long long a,
                                                    unsigned long long b) {
    unsigned long long d;
    asm("add.rn.f32x2 %0, %1, %2;" : "=l"(d) : "l"(a), "l"(b));
    return d;
}

// Packed constants for polynomial exp: 2^f via deg-4 Taylor in ln2,
// f in [-0.5,0.5] (rel err ~4e-5 << bucket width 2^-9). Magic = 1.5*2^23.
#define PKC(x) ((((unsigned long long)__float_as_uint(x)) << 32) | __float_as_uint(x))

// ---------------------------------------------------------------------------
// Kernel 1: fused softmax + histogram build (R9-proven; FROZEN — it sits at
// the spread-REDG lane-throughput floor: 20M REDs x 1.29 cyc/lane / 148 SMs).
// NOTE: targets are int32 on device (JAX x64 disabled).
// ---------------------------------------------------------------------------
__global__ __launch_bounds__(256) void build_hist_kernel(
        const float* __restrict__ logits,
        const int* __restrict__ targets) {
    int p = blockIdx.x * blockDim.x + threadIdx.x;
    int b  = p >> 18;          // p / HW
    int hw = p & (HW - 1);
    const float* base = logits + (size_t)b * C_CLS * HW + hw;

    const unsigned long long L2E2 = PKC(1.4426950408889634f);
    const unsigned long long MAG2 = PKC(12582912.0f);
    const unsigned long long C4   = PKC(0.009618129f);
    const unsigned long long C3   = PKC(0.055504109f);
    const unsigned long long C2   = PKC(0.240226507f);
    const unsigned long long C1   = PKC(0.693147181f);
    const unsigned long long C0   = PKC(1.0f);
    const unsigned long long SGN2 = 0x8000000080000000ull;

    float e[C_CLS];
#pragma unroll
    for (int c = 0; c < 11; c++) {
        e[c] = __expf(base[(size_t)c * HW]);
    }
#pragma unroll
    for (int j = 0; j < 4; j++) {
        int ca = 11 + 2 * j;
        unsigned long long x2 = pk2(base[(size_t)ca * HW],
                                    base[(size_t)(ca + 1) * HW]);
        unsigned long long t2 = ffma2(x2, L2E2, MAG2);
        unsigned long long mt2 = fadd2(MAG2, t2 ^ SGN2);
        unsigned long long f2 = ffma2(x2, L2E2, mt2);
        unsigned long long p2 = ffma2(C4, f2, C3);
        p2 = ffma2(p2, f2, C2);
        p2 = ffma2(p2, f2, C1);
        p2 = ffma2(p2, f2, C0);
        uint32_t tlo = (uint32_t)t2, thi = (uint32_t)(t2 >> 32);
        uint32_t plo = (uint32_t)p2, phi = (uint32_t)(p2 >> 32);
        e[ca]     = __uint_as_float(plo + (tlo << 23));
        e[ca + 1] = __uint_as_float(phi + (thi << 23));
    }

    float s = 0.0f;
#pragma unroll
    for (int c = 0; c < C_CLS; c++) s += e[c];
    float inv = __fdividef(1.0f, s);
    int t = targets[p];

#pragma unroll
    for (int c = 0; c < C_CLS; c++) {
        float pr = e[c] * inv;
        bool gt = (t == c);
        float err = gt ? (1.0f - pr) : pr;
        uint32_t q  = (__float_as_uint(err) << 2) >> 16;   // bits[29:14]
        uint32_t qd = QMASK - q;                           // descending order
        uint32_t qs = __brev(qd) >> 16;                    // 16-bit reversal
        uint32_t idx = ((uint32_t)c << QBITS) | qs;
        atomicAdd(&g_hist[idx], gt ? 0x10001u : 1u);
    }
}

// ---------------------------------------------------------------------------
// Kernel 2: fused chunk-reduce + grid-sync + scan + Lovasz eval + output.
//
// Phase 1: each block gathers its chunk's 4096 buckets (16/thread, registers)
//          and block-scans to get thread offsets + the chunk sum.
// Sync:    release (threadfence + counter inc); thread 0 spins until all
//          NCHUNK counters arrive. RESIDENCY INVARIANT: __launch_bounds__
//          (256,4) caps regs at 64 -> 4 blocks/SM x 148 = 592 >= 304 grid
//          blocks, so every block is wave-1 resident and the spin is safe.
// Phase 2: warp 0 shfl-scans the class's 16 chunk sums (ld.cg, L1-bypassed)
//          -> class offset + gt total n; per-bucket telescoped closed form:
//          e * (J(p1,cs1) - J(r0,cs0)), J(p,cs) = p/(n+p-cs), J(0,.) = 0,
//          exact int64 numerator. Block-reduce -> atomic double.
// Output:  last block (2nd counter) writes out[0]. No finalize kernel.
//
// qd = kk*4096 + t*16 + j (4+8+4 bits) -> rev16(qd) = rev4(kk) + 16*rev8(t)
// + 4096*rev4(j); rev4(j) constant-folds in the unrolled loop.
// ---------------------------------------------------------------------------
__global__ __launch_bounds__(256, 4) void fused_eval_kernel(
        float* __restrict__ out) {
    typedef cub::BlockScan<unsigned long long, 256> BS;
    __shared__ typename BS::TempStorage ts;
    __shared__ double red[256];
    __shared__ unsigned long long sOff;
    __shared__ uint32_t sN;

    int chunk = blockIdx.x;
    uint32_t c  = (uint32_t)chunk >> 4;
    uint32_t kk = (uint32_t)chunk & 15u;
    uint32_t cls = c << QBITS;
    uint32_t r4kk = __brev(kk) >> 28;
    uint32_t r8t  = __brev((uint32_t)threadIdx.x) >> 24;
    uint32_t sbase = cls + r4kk + 16u * r8t;

    // Phase 1: gather chunk (stays in registers) + block scan
    uint32_t h[16];
    unsigned long long localSum = 0ull;
#pragma unroll
    for (int j = 0; j < 16; j++) {
        uint32_t r4j = __brev((uint32_t)j) >> 28;          // constant-folded
        uint32_t v = g_hist[sbase + (r4j << 12)];
        h[j] = v;
        localSum += (v & 0xFFFFu) + ((unsigned long long)(v >> 16) << 32);
    }
    unsigned long long thrOff, blockAgg;
    BS(ts).ExclusiveSum(localSum, thrOff, blockAgg);

    // Release: publish chunk sum, then signal.
    if (threadIdx.x == 0) {
        g_chunkSum[chunk] = blockAgg;
        __threadfence();
        atomicAdd(&g_sync.done, 1u);
        // Acquire: wait for all chunks.
        while (atomicAdd(&g_sync.done, 0u) < (unsigned)NCHUNK)
            __nanosleep(64);
    }
    __syncthreads();

    // Phase 2: per-class prefix over 16 chunk sums (warp 0; ld.cg bypasses
    // L1 so we see the other blocks' L2-visible writes).
    if (threadIdx.x < 16) {
        unsigned long long v = __ldcg(&g_chunkSum[c * 16u + threadIdx.x]);
        unsigned long long inc = v;
#pragma unroll
        for (int o = 1; o < 16; o <<= 1) {
            unsigned long long up = __shfl_up_sync(0xFFFFu, inc, o);
            if ((int)threadIdx.x >= o) inc += up;
        }
        if (threadIdx.x == kk) sOff = inc - v;           // exclusive at kk
        if (threadIdx.x == 15) sN = (uint32_t)(inc >> 32);
    }
    __syncthreads();
    uint32_t n = sN;
    unsigned long long run = sOff + thrOff;

    uint32_t qd_base = kk * (uint32_t)CHUNK + (uint32_t)threadIdx.x * 16u;
    double acc = 0.0;
#pragma unroll
    for (int j = 0; j < 16; j++) {
        uint32_t hv = h[j];
        if (hv != 0u) {
            uint32_t r0  = (uint32_t)run;
            uint32_t cs0 = (uint32_t)(run >> 32);
            uint32_t m   = hv & 0xFFFFu;
            uint32_t g   = hv >> 16;
            uint32_t p1  = r0 + m;
            uint32_t cs1 = cs0 + g;
            float diff;
            if (r0 == 0u) {
                diff = (float)p1 / (float)(n + p1 - cs1);
            } else {
                long long num = (long long)p1 * (long long)(n + r0 - cs0)
                              - (long long)r0 * (long long)(n + p1 - cs1);
                float den = (float)((double)(n + p1 - cs1) *
                                    (double)(n + r0 - cs0));
                diff = (float)num / den;
            }
            uint32_t q = QMASK - (qd_base + (uint32_t)j);
            float e = __uint_as_float((q << 14) | 0x2000u);  // bucket midpoint
            acc += (double)e * (double)diff;
            run += m + ((unsigned long long)g << 32);
        }
    }

    red[threadIdx.x] = acc;
    __syncthreads();
#pragma unroll
    for (int o = 128; o > 0; o >>= 1) {
        if (threadIdx.x < o) red[threadIdx.x] += red[threadIdx.x + o];
        __syncthreads();
    }
    if (threadIdx.x == 0) {
        atomicAdd(&g_sync.loss, red[0]);
        __threadfence();
        unsigned int old = atomicAdd(&g_sync.done2, 1u);
        if (old == (unsigned)NCHUNK - 1u) {
            // Last block: all loss adds are L2-visible (fence + counter).
            double total = atomicAdd(&g_sync.loss, 0.0);
            out[0] = (float)(total / (double)C_CLS);
        }
    }
}

// ---------------------------------------------------------------------------
// Host launcher (graph-capturable; no allocation, no sync). 4 graph nodes.
// ---------------------------------------------------------------------------
extern "C" void kernel_launch(void* const* d_in, const int* in_sizes, int n_in,
                              void* d_out, int out_size) {
    const float* logits = (const float*)d_in[0];
    const int* targs    = (const int*)d_in[1];
    float* out = (float*)d_out;

    uint32_t* hist;
    void* syncp;
    cudaGetSymbolAddress((void**)&hist, g_hist);
    cudaGetSymbolAddress(&syncp, g_sync);

    cudaMemsetAsync(hist, 0, (size_t)NB * sizeof(uint32_t), 0);
    cudaMemsetAsync(syncp, 0, 16, 0);

    build_hist_kernel<<<P_PIX / 256, 256>>>(logits, targs);
    fused_eval_kernel<<<NCHUNK, 256>>>(out);
}

// round 12
// speedup vs baseline: 1.0676x; 1.0676x over previous
#include <cuda_runtime.h>
#include <cstdint>
#include <cub/block/block_scan.cuh>

// Problem constants (fixed shapes from reference)
#define B_BATCH 4
#define C_CLS   19
#define HW      (512 * 512)            // 262144
#define P_PIX   (B_BATCH * HW)         // 1048576

// 16-bit quantization of err in [0,1]: fp32 bits[29:14] (7 exp + 9 mantissa),
// extracted sign-safely as (bits<<2)>>16. Measured loss error 6.3e-8.
#define QBITS 16
#define NB_PER_CLASS (1 << QBITS)          // 65536
#define QMASK (NB_PER_CLASS - 1)
#define NB (C_CLS * NB_PER_CLASS)          // 1,245,184

// Eval decomposition: 64 chunks of 1024 buckets per class.
#define ECHUNK 1024
#define ECH_PER_CLASS 64
#define NECHUNK (C_CLS * ECH_PER_CLASS)    // 1216

// Histogram: u32 per bucket, packed cnt | gt<<16. Bucket ids stored
// BIT-REVERSED (self-inverse): the 8 buckets per 32B L2 sector are qd values
// 8192 apart -> concurrent REDs never serialize on a sector (R8/R9-proven).
// Layout algebra (qd = kk[6]:t[8]:j[2], s = rev16(qd)):
//   s = rev6(kk) + rev8(t)*64 + rev2(j)*16384
// and for any contiguous s: chunk kk = rev6(s & 63) -> chunk sums are
// computable from fully-coalesced contiguous reads (sum is commutative).
__device__ __align__(16) uint32_t g_hist[NB];
__device__ unsigned long long g_chunkSum[NECHUNK];   // atomically accumulated
__device__ struct { unsigned int done2; unsigned int pad; double loss; } g_sync;

// ---------------------------------------------------------------------------
// f32x2 packed-math helpers (FFMA2: 2 fp32 FMAs per issue slot)
// ---------------------------------------------------------------------------
__device__ __forceinline__ unsigned long long pk2(float lo, float hi) {
    unsigned long long r;
    asm("mov.b64 %0, {%1, %2};" : "=l"(r) : "f"(lo), "f"(hi));
    return r;
}
__device__ __forceinline__ unsigned long long ffma2(unsigned long long a,
                                                    unsigned long long b,
                                                    unsigned long long c) {
    unsigned long long d;
    asm("fma.rn.f32x2 %0, %1, %2, %3;" : "=l"(d) : "l"(a), "l"(b), "l"(c));
    return d;
}
__device__ __forceinline__ unsigned long long fadd2(unsigned long long a,
                                                    unsigned long long b) {
    unsigned long long d;
    asm("add.rn.f32x2 %0, %1, %2;" : "=l"(d) : "l"(a), "l"(b));
    return d;
}

// Packed constants for polynomial exp: 2^f via deg-4 Taylor in ln2,
// f in [-0.5,0.5] (rel err ~4e-5 << bucket width 2^-9). Magic = 1.5*2^23.
#define PKC(x) ((((unsigned long long)__float_as_uint(x)) << 32) | __float_as_uint(x))

// ---------------------------------------------------------------------------
// Kernel 1: fused softmax + histogram build (R9-proven; FROZEN — it sits at
// the spread-REDG lane-throughput floor: 20M REDs x 1.29 cyc/lane / 148 SMs).
// NOTE: targets are int32 on device (JAX x64 disabled).
// ---------------------------------------------------------------------------
__global__ __launch_bounds__(256) void build_hist_kernel(
        const float* __restrict__ logits,
        const int* __restrict__ targets) {
    int p = blockIdx.x * blockDim.x + threadIdx.x;
    int b  = p >> 18;          // p / HW
    int hw = p & (HW - 1);
    const float* base = logits + (size_t)b * C_CLS * HW + hw;

    const unsigned long long L2E2 = PKC(1.4426950408889634f);
    const unsigned long long MAG2 = PKC(12582912.0f);
    const unsigned long long C4   = PKC(0.009618129f);
    const unsigned long long C3   = PKC(0.055504109f);
    const unsigned long long C2   = PKC(0.240226507f);
    const unsigned long long C1   = PKC(0.693147181f);
    const unsigned long long C0   = PKC(1.0f);
    const unsigned long long SGN2 = 0x8000000080000000ull;

    float e[C_CLS];
#pragma unroll
    for (int c = 0; c < 11; c++) {
        e[c] = __expf(base[(size_t)c * HW]);
    }
#pragma unroll
    for (int j = 0; j < 4; j++) {
        int ca = 11 + 2 * j;
        unsigned long long x2 = pk2(base[(size_t)ca * HW],
                                    base[(size_t)(ca + 1) * HW]);
        unsigned long long t2 = ffma2(x2, L2E2, MAG2);
        unsigned long long mt2 = fadd2(MAG2, t2 ^ SGN2);
        unsigned long long f2 = ffma2(x2, L2E2, mt2);
        unsigned long long p2 = ffma2(C4, f2, C3);
        p2 = ffma2(p2, f2, C2);
        p2 = ffma2(p2, f2, C1);
        p2 = ffma2(p2, f2, C0);
        uint32_t tlo = (uint32_t)t2, thi = (uint32_t)(t2 >> 32);
        uint32_t plo = (uint32_t)p2, phi = (uint32_t)(p2 >> 32);
        e[ca]     = __uint_as_float(plo + (tlo << 23));
        e[ca + 1] = __uint_as_float(phi + (thi << 23));
    }

    float s = 0.0f;
#pragma unroll
    for (int c = 0; c < C_CLS; c++) s += e[c];
    float inv = __fdividef(1.0f, s);
    int t = targets[p];

#pragma unroll
    for (int c = 0; c < C_CLS; c++) {
        float pr = e[c] * inv;
        bool gt = (t == c);
        float err = gt ? (1.0f - pr) : pr;
        uint32_t q  = (__float_as_uint(err) << 2) >> 16;   // bits[29:14]
        uint32_t qd = QMASK - q;                           // descending order
        uint32_t qs = __brev(qd) >> 16;                    // 16-bit reversal
        uint32_t idx = ((uint32_t)c << QBITS) | qs;
        atomicAdd(&g_hist[idx], gt ? 0x10001u : 1u);
    }
}

// ---------------------------------------------------------------------------
// Kernel 2: COALESCED chunk-sum reduction. 304 blocks (19 classes x 16
// contiguous 4096-word slabs). Each thread reads 16 consecutive scrambled
// words (4x uint4, fully coalesced); word at scrambled offset s belongs to
// eval-chunk kk = rev6(s & 63). Thread's 16 words cover residues
// 16*(t&3)..+15; shfl-reduce over lanes with equal (t&3) (offsets 4,8,16),
// then lanes 0..3 flush 16 u64 atomics each. Block 0 also zeroes g_sync.
// ---------------------------------------------------------------------------
__global__ __launch_bounds__(256) void chunk_reduce_kernel() {
    uint32_t cls19 = (uint32_t)blockIdx.x >> 4;
    uint32_t slab  = (uint32_t)blockIdx.x & 15u;
    if (blockIdx.x == 0 && threadIdx.x == 0) {
        g_sync.loss = 0.0;
        g_sync.done2 = 0u;
    }
    const uint4* p = (const uint4*)(g_hist + (cls19 << QBITS) + slab * 4096u
                                    + (uint32_t)threadIdx.x * 16u);
    unsigned long long part[16];
#pragma unroll
    for (int i = 0; i < 16; i++) part[i] = 0ull;
#pragma unroll
    for (int v = 0; v < 4; v++) {
        uint4 w = p[v];
        part[v*4+0] += (w.x & 0xFFFFu) + ((unsigned long long)(w.x >> 16) << 32);
        part[v*4+1] += (w.y & 0xFFFFu) + ((unsigned long long)(w.y >> 16) << 32);
        part[v*4+2] += (w.z & 0xFFFFu) + ((unsigned long long)(w.z >> 16) << 32);
        part[v*4+3] += (w.w & 0xFFFFu) + ((unsigned long long)(w.w >> 16) << 32);
    }
    // Reduce over the 8 lanes sharing (lane & 3)
#pragma unroll
    for (int i = 0; i < 16; i++) {
#pragma unroll
        for (int o = 4; o <= 16; o <<= 1)
            part[i] += __shfl_down_sync(0xFFFFFFFFu, part[i], o);
    }
    uint32_t lane = (uint32_t)threadIdx.x & 31u;
    if (lane < 4u) {
#pragma unroll
        for (int i = 0; i < 16; i++) {
            uint32_t res = (lane << 4) + (uint32_t)i;     // s & 63
            uint32_t kk  = __brev(res) >> 26;             // rev6
            atomicAdd(&g_chunkSum[cls19 * 64u + kk], part[i]);
        }
    }
}

// ---------------------------------------------------------------------------
// Kernel 3: eval. 1216 blocks (19 classes x 64 chunks of 1024 buckets).
// Warp 0: two-register shfl scan of the class's 64 chunk sums -> this
// chunk's exclusive offset + class gt-total n. Then 4 gathers/thread
// (s = rev6(kk) + rev8(t)*64 + rev2(j)*16384), BlockScan, and the telescoped
// per-bucket closed form with exact int64 numerator:
//   e * (J(p1,cs1) - J(r0,cs0)),  J(p,cs) = p / (n + p - cs),  J(0,.) = 0.
// Terms are all >= 0 -> float accumulation is well-conditioned; cross-block
// combine in double. Last block (counter) writes out[0] — non-blocking, no
// residency requirement.
// ---------------------------------------------------------------------------
__global__ __launch_bounds__(256) void eval_kernel(float* __restrict__ out) {
    typedef cub::BlockScan<unsigned long long, 256> BS;
    __shared__ typename BS::TempStorage ts;
    __shared__ float red[256];
    __shared__ unsigned long long sOff;
    __shared__ uint32_t sN;

    uint32_t c  = (uint32_t)blockIdx.x >> 6;
    uint32_t kk = (uint32_t)blockIdx.x & 63u;

    if (threadIdx.x < 32) {
        uint32_t lane = threadIdx.x;
        unsigned long long a = g_chunkSum[c * 64u + lane];
        unsigned long long b = g_chunkSum[c * 64u + 32u + lane];
        unsigned long long ai = a, bi = b;
#pragma unroll
        for (int o = 1; o < 32; o <<= 1) {
            unsigned long long ua = __shfl_up_sync(0xFFFFFFFFu, ai, o);
            unsigned long long ub = __shfl_up_sync(0xFFFFFFFFu, bi, o);
            if ((int)lane >= o) { ai += ua; bi += ub; }
        }
        unsigned long long totA = __shfl_sync(0xFFFFFFFFu, ai, 31);
        uint32_t kl = kk & 31u;
        unsigned long long inclK, origK;
        if (kk < 32u) {
            inclK = __shfl_sync(0xFFFFFFFFu, ai, kl);
            origK = __shfl_sync(0xFFFFFFFFu, a, kl);
        } else {
            inclK = totA + __shfl_sync(0xFFFFFFFFu, bi, kl);
            origK = __shfl_sync(0xFFFFFFFFu, b, kl);
        }
        unsigned long long tot = totA + __shfl_sync(0xFFFFFFFFu, bi, 31);
        if (lane == 0) {
            sOff = inclK - origK;               // exclusive prefix at kk
            sN = (uint32_t)(tot >> 32);
        }
    }
    __syncthreads();
    uint32_t n = sN;

    // Gathers: qd = kk*1024 + t*4 + j  ->  s = rev6(kk) + rev8(t)*64 + rev2(j)*16384
    uint32_t sbase = (c << QBITS) + (__brev(kk) >> 26)
                   + ((__brev((uint32_t)threadIdx.x) >> 24) << 6);
    const uint32_t rev2[4] = {0u, 2u, 1u, 3u};
    uint32_t h[4];
    unsigned long long localSum = 0ull;
#pragma unroll
    for (int j = 0; j < 4; j++) {
        uint32_t v = g_hist[sbase + (rev2[j] << 14)];
        h[j] = v;
        localSum += (v & 0xFFFFu) + ((unsigned long long)(v >> 16) << 32);
    }

    unsigned long long thrOff;
    BS(ts).ExclusiveSum(localSum, thrOff);
    unsigned long long run = sOff + thrOff;

    uint32_t qd_base = kk * (uint32_t)ECHUNK + (uint32_t)threadIdx.x * 4u;
    float acc = 0.0f;
#pragma unroll
    for (int j = 0; j < 4; j++) {
        uint32_t hv = h[j];
        if (hv != 0u) {
            uint32_t r0  = (uint32_t)run;
            uint32_t cs0 = (uint32_t)(run >> 32);
            uint32_t m   = hv & 0xFFFFu;
            uint32_t g   = hv >> 16;
            uint32_t p1  = r0 + m;
            uint32_t cs1 = cs0 + g;
            float diff;
            if (r0 == 0u) {
                diff = (float)p1 / (float)(n + p1 - cs1);
            } else {
                long long num = (long long)p1 * (long long)(n + r0 - cs0)
                              - (long long)r0 * (long long)(n + p1 - cs1);
                float den = (float)((double)(n + p1 - cs1) *
                                    (double)(n + r0 - cs0));
                diff = (float)num / den;
            }
            uint32_t q = QMASK - (qd_base + (uint32_t)j);
            float e = __uint_as_float((q << 14) | 0x2000u);  // bucket midpoint
            acc += e * diff;                                  // all terms >= 0
            run += m + ((unsigned long long)g << 32);
        }
    }

    red[threadIdx.x] = acc;
    __syncthreads();
#pragma unroll
    for (int o = 128; o > 0; o >>= 1) {
        if (threadIdx.x < o) red[threadIdx.x] += red[threadIdx.x + o];
        __syncthreads();
    }
    if (threadIdx.x == 0) {
        atomicAdd(&g_sync.loss, (double)red[0]);
        __threadfence();
        unsigned int old = atomicAdd(&g_sync.done2, 1u);
        if (old == (unsigned)NECHUNK - 1u) {
            double total = atomicAdd(&g_sync.loss, 0.0);
            out[0] = (float)(total / (double)C_CLS);
        }
    }
}

// ---------------------------------------------------------------------------
// Host launcher (graph-capturable; no allocation, no sync). 5 graph nodes.
// ---------------------------------------------------------------------------
extern "C" void kernel_launch(void* const* d_in, const int* in_sizes, int n_in,
                              void* d_out, int out_size) {
    const float* logits = (const float*)d_in[0];
    const int* targs    = (const int*)d_in[1];
    float* out = (float*)d_out;

    uint32_t* hist;
    unsigned long long* csum;
    cudaGetSymbolAddress((void**)&hist, g_hist);
    cudaGetSymbolAddress((void**)&csum, g_chunkSum);

    cudaMemsetAsync(hist, 0, (size_t)NB * sizeof(uint32_t), 0);
    cudaMemsetAsync(csum, 0, (size_t)NECHUNK * sizeof(unsigned long long), 0);

    build_hist_kernel<<<P_PIX / 256, 256>>>(logits, targs);
    chunk_reduce_kernel<<<C_CLS * 16, 256>>>();
    eval_kernel<<<NECHUNK, 256>>>(out);
}